// round 1
// baseline (speedup 1.0000x reference)
#include <cuda_runtime.h>
#include <cuda_bf16.h>

// Problem constants
#define B     16
#define CIN   256
#define COUT  256
#define Hdim  64
#define Wdim  64
#define STY   512
#define CIC   8          // ci chunk per smem stage

// Scratch (allocation-free rule: __device__ globals)
__device__ float g_s[B * CIN];                                   // style scales
__device__ float g_wgt[(size_t)B * CIN * 9 * COUT];              // [b][ci][tap][co], co fastest

// ---------------------------------------------------------------------------
// Kernel 1: s[b][ci] = dot(w_style[b,:], aff_w[ci,:]) + aff_b[ci] + 1
// one warp per (b,ci), float4 loads
// ---------------------------------------------------------------------------
__global__ void style_kernel(const float* __restrict__ w_style,
                             const float* __restrict__ aff_w,
                             const float* __restrict__ aff_b) {
    int warp = blockIdx.x * (blockDim.x >> 5) + (threadIdx.x >> 5);
    int lane = threadIdx.x & 31;
    if (warp >= B * CIN) return;
    int b  = warp / CIN;
    int ci = warp % CIN;
    const float4* ws = reinterpret_cast<const float4*>(w_style + (size_t)b * STY);
    const float4* aw = reinterpret_cast<const float4*>(aff_w  + (size_t)ci * STY);
    float sum = 0.f;
    #pragma unroll
    for (int j = lane; j < STY / 4; j += 32) {
        float4 a = ws[j], c = aw[j];
        sum += a.x * c.x + a.y * c.y + a.z * c.z + a.w * c.w;
    }
    #pragma unroll
    for (int o = 16; o; o >>= 1) sum += __shfl_xor_sync(0xffffffffu, sum, o);
    if (lane == 0) g_s[b * CIN + ci] = sum + aff_b[ci] + 1.0f;
}

// ---------------------------------------------------------------------------
// Kernel 2: modulate + demodulate.
// block (co, b); thread = ci. Each thread owns the 9 taps of one ci row.
// Writes g_wgt in [b][ci][tap][co] layout (co contiguous for the conv).
// ---------------------------------------------------------------------------
__global__ void modulate_kernel(const float* __restrict__ Wf) {
    int co = blockIdx.x;
    int b  = blockIdx.y;
    int ci = threadIdx.x;

    float s = g_s[b * CIN + ci];
    const float* wp = Wf + ((size_t)co * CIN + ci) * 9;
    float m[9];
    float ss = 0.f;
    #pragma unroll
    for (int t = 0; t < 9; t++) {
        m[t] = wp[t] * s;
        ss += m[t] * m[t];
    }

    __shared__ float red[256];
    red[ci] = ss;
    __syncthreads();
    #pragma unroll
    for (int st = 128; st > 0; st >>= 1) {
        if (ci < st) red[ci] += red[ci + st];
        __syncthreads();
    }
    float d = rsqrtf(red[0] + 1e-8f);

    float* op = g_wgt + ((size_t)(b * CIN + ci) * 9) * COUT + co;
    #pragma unroll
    for (int t = 0; t < 9; t++) op[(size_t)t * COUT] = m[t] * d;
}

// ---------------------------------------------------------------------------
// Kernel 3: direct conv, per-sample weights from g_wgt.
// grid: (16 spatial tiles of 16x16, 4 co-tiles of 64, 16 batch)
// block: 256 threads = 32 pixel-lanes x 8 co-groups
// each thread: 8 co x 8 px register tile, ci staged in chunks of 8.
// ---------------------------------------------------------------------------
__global__ void __launch_bounds__(256)
conv_kernel(const float* __restrict__ x, float* __restrict__ out) {
    __shared__ float xs[CIC][18][18];   // input tile + halo
    __shared__ float ws[CIC][9][64];    // weights [ci][tap][co]

    const int tid = threadIdx.x;
    const int tx  = tid & 31;           // pixel lane
    const int ty  = tid >> 5;           // co group (0..7)

    const int tileY = (blockIdx.x >> 2) * 16;
    const int tileX = (blockIdx.x & 3) * 16;
    const int coBase = blockIdx.y * 64;
    const int b = blockIdx.z;

    // per-thread pixel coordinates within the 16x16 tile
    int soff[8];   // smem offset (row*18 + col) at tap (0,0)
    int goff[8];   // global offset within output image plane
    #pragma unroll
    for (int p = 0; p < 8; p++) {
        int pix = tx + 32 * p;
        int py = pix >> 4, px = pix & 15;
        soff[p] = py * 18 + px;
        goff[p] = (tileY + py) * Wdim + (tileX + px);
    }

    float acc[8][8];
    #pragma unroll
    for (int i = 0; i < 8; i++)
        #pragma unroll
        for (int p = 0; p < 8; p++) acc[i][p] = 0.f;

    const float* xb = x + (size_t)b * CIN * Hdim * Wdim;
    const float* wb = g_wgt + (size_t)b * CIN * 9 * COUT;

    for (int cc = 0; cc < CIN; cc += CIC) {
        // stage x tile (with zero-padded halo)
        for (int idx = tid; idx < CIC * 18 * 18; idx += 256) {
            int ci  = idx / 324;
            int rem = idx - ci * 324;
            int r = rem / 18, c = rem - r * 18;
            int gy = tileY + r - 1, gx = tileX + c - 1;
            float v = 0.f;
            if ((unsigned)gy < (unsigned)Hdim && (unsigned)gx < (unsigned)Wdim)
                v = xb[(size_t)(cc + ci) * (Hdim * Wdim) + gy * Wdim + gx];
            xs[ci][r][c] = v;
        }
        // stage weights (coalesced: co fastest in g_wgt)
        for (int idx = tid; idx < CIC * 9 * 64; idx += 256) {
            int co  = idx & 63;
            int t2  = idx >> 6;
            int tap = t2 % 9;
            int ci  = t2 / 9;
            ws[ci][tap][co] = wb[((size_t)(cc + ci) * 9 + tap) * COUT + coBase + co];
        }
        __syncthreads();

        #pragma unroll 1
        for (int ci = 0; ci < CIC; ci++) {
            const float* xrow = &xs[ci][0][0];
            #pragma unroll
            for (int kh = 0; kh < 3; kh++) {
                #pragma unroll
                for (int kw = 0; kw < 3; kw++) {
                    float wv[8];
                    #pragma unroll
                    for (int i = 0; i < 8; i++)
                        wv[i] = ws[ci][kh * 3 + kw][ty + 8 * i];
                    float xv[8];
                    #pragma unroll
                    for (int p = 0; p < 8; p++)
                        xv[p] = xrow[soff[p] + kh * 18 + kw];
                    #pragma unroll
                    for (int i = 0; i < 8; i++)
                        #pragma unroll
                        for (int p = 0; p < 8; p++)
                            acc[i][p] = fmaf(wv[i], xv[p], acc[i][p]);
                }
            }
        }
        __syncthreads();
    }

    float* ob = out + (size_t)b * COUT * Hdim * Wdim;
    #pragma unroll
    for (int i = 0; i < 8; i++) {
        int co = coBase + ty + 8 * i;
        float* orow = ob + (size_t)co * (Hdim * Wdim);
        #pragma unroll
        for (int p = 0; p < 8; p++)
            orow[goff[p]] = acc[i][p];
    }
}

// ---------------------------------------------------------------------------
extern "C" void kernel_launch(void* const* d_in, const int* in_sizes, int n_in,
                              void* d_out, int out_size) {
    const float* x       = (const float*)d_in[0];   // [16,256,64,64]
    const float* w_style = (const float*)d_in[1];   // [16,512]
    const float* Wf      = (const float*)d_in[2];   // [256,256,3,3]
    const float* aff_w   = (const float*)d_in[3];   // [256,512]
    const float* aff_b   = (const float*)d_in[4];   // [256]
    float* out = (float*)d_out;                     // [16,256,64,64]

    style_kernel<<<(B * CIN + 7) / 8, 256>>>(w_style, aff_w, aff_b);
    modulate_kernel<<<dim3(COUT, B), 256>>>(Wf);
    conv_kernel<<<dim3(16, 4, B), 256>>>(x, out);
}